// round 1
// baseline (speedup 1.0000x reference)
#include <cuda_runtime.h>
#include <cuda_bf16.h>
#include <math.h>

#define NUM_N 100000
#define NUM_E 1600000
#define NUM_G 128
#define D_IN 128
#define D_H1 16
#define D_H2 128

#define SCAN_B 1024
#define SCAN_NB ((NUM_N + SCAN_B - 1) / SCAN_B)

// -------- device scratch (no allocations allowed) --------
__device__ int   g_flag64;
__device__ int   g_src[NUM_E];
__device__ int   g_dst[NUM_E];
__device__ int   g_batch[NUM_N];
__device__ int   g_deg[NUM_N];      // in-degree (excl self loop)
__device__ float g_dinv[NUM_N];
__device__ int   g_off[NUM_N];      // CSR offsets (exclusive scan of deg)
__device__ int   g_cnt[NUM_N];      // scatter counters
__device__ int   g_csrc[NUM_E];     // src ids sorted by dst
__device__ int   g_bsum[SCAN_NB + 8];
__device__ int   g_pcnt[NUM_G];     // nodes per graph
__device__ int   g_boff[NUM_G];     // batch CSR offsets
__device__ int   g_bcnt2[NUM_G];
__device__ int   g_bnode[NUM_N];    // node ids grouped by graph
__device__ float g_h1[NUM_N * D_H1];   // (x@W1)*dinv
__device__ float g_q [NUM_N * D_H1];   // relu(layer1)*dinv
__device__ float g_r [NUM_N * D_H1];   // aggregated layer2 input (16-dim)
__device__ float g_pool[NUM_G * D_H2];

// -------- 0: zero init --------
__global__ void zero_kernel() {
    int i = blockIdx.x * blockDim.x + threadIdx.x;
    if (i < NUM_N) { g_deg[i] = 0; g_cnt[i] = 0; }
    if (i < NUM_G) { g_pcnt[i] = 0; g_bcnt2[i] = 0; }
    if (i == 0) g_flag64 = 1;
}

// -------- 1: detect int64 vs int32 index layout --------
__global__ void detect_kernel(const void* ei) {
    int i = blockIdx.x * blockDim.x + threadIdx.x; // 2048 samples
    long long v = ((const long long*)ei)[i];
    if (v < 0 || v >= (long long)NUM_N) atomicAnd(&g_flag64, 0);
}

// -------- 2: convert indices + degree/batch histograms --------
__global__ void convert_kernel(const void* ei, const void* bat) {
    int i = blockIdx.x * blockDim.x + threadIdx.x;
    bool f64 = (g_flag64 != 0);
    if (i < NUM_E) {
        int s, d;
        if (f64) {
            s = (int)((const long long*)ei)[i];
            d = (int)((const long long*)ei)[NUM_E + i];
        } else {
            s = ((const int*)ei)[i];
            d = ((const int*)ei)[NUM_E + i];
        }
        g_src[i] = s;
        g_dst[i] = d;
        atomicAdd(&g_deg[d], 1);
    }
    if (i < NUM_N) {
        int b = f64 ? (int)((const long long*)bat)[i] : ((const int*)bat)[i];
        g_batch[i] = b;
        atomicAdd(&g_pcnt[b], 1);
    }
}

// -------- 3: dinv = rsqrt(deg+1) --------
__global__ void dinv_kernel() {
    int i = blockIdx.x * blockDim.x + threadIdx.x;
    if (i < NUM_N) g_dinv[i] = rsqrtf((float)(g_deg[i] + 1));
}

// -------- 4: exclusive scan of deg -> g_off --------
__global__ void scan1_kernel() {
    __shared__ int sh[SCAN_B];
    int t = threadIdx.x;
    int i = blockIdx.x * SCAN_B + t;
    int v = (i < NUM_N) ? g_deg[i] : 0;
    sh[t] = v;
    __syncthreads();
    for (int off = 1; off < SCAN_B; off <<= 1) {
        int a = (t >= off) ? sh[t - off] : 0;
        __syncthreads();
        sh[t] += a;
        __syncthreads();
    }
    if (i < NUM_N) g_off[i] = sh[t] - v;
    if (t == SCAN_B - 1) g_bsum[blockIdx.x] = sh[t];
}

__global__ void scan2_kernel() {
    if (threadIdx.x == 0 && blockIdx.x == 0) {
        int run = 0;
        for (int i = 0; i < SCAN_NB; i++) { int v = g_bsum[i]; g_bsum[i] = run; run += v; }
    }
}

__global__ void scan3_kernel() {
    int i = blockIdx.x * SCAN_B + threadIdx.x;
    if (i < NUM_N) g_off[i] += g_bsum[blockIdx.x];
}

// -------- 5: scatter edges into dst-CSR --------
__global__ void escatter_kernel() {
    int i = blockIdx.x * blockDim.x + threadIdx.x;
    if (i < NUM_E) {
        int d = g_dst[i];
        int pos = g_off[d] + atomicAdd(&g_cnt[d], 1);
        g_csrc[pos] = g_src[i];
    }
}

// -------- 6: batch CSR --------
__global__ void bscan_kernel() {
    if (threadIdx.x == 0 && blockIdx.x == 0) {
        int run = 0;
        for (int gph = 0; gph < NUM_G; gph++) { g_boff[gph] = run; run += g_pcnt[gph]; }
    }
}

__global__ void bscatter_kernel() {
    int i = blockIdx.x * blockDim.x + threadIdx.x;
    if (i < NUM_N) {
        int b = g_batch[i];
        int pos = g_boff[b] + atomicAdd(&g_bcnt2[b], 1);
        g_bnode[pos] = i;
    }
}

// -------- 7: GEMM1: h1 = (x @ W1) * dinv   [N,128]@[128,16] --------
__global__ void gemm1_kernel(const float* __restrict__ x, const float* __restrict__ W1) {
    __shared__ float4 w1s[D_IN * 4];   // W1[k][j]: 4 float4 per k
    for (int i = threadIdx.x; i < D_IN * 4; i += blockDim.x)
        w1s[i] = ((const float4*)W1)[i];
    __syncthreads();
    int w = (blockIdx.x * blockDim.x + threadIdx.x) >> 5;
    if (w >= NUM_N) return;
    int lane = threadIdx.x & 31;
    float4 xv = ((const float4*)x)[w * 32 + lane];  // k = 4*lane .. 4*lane+3
    float xk[4] = {xv.x, xv.y, xv.z, xv.w};
    float a[16];
    #pragma unroll
    for (int j = 0; j < 16; j++) a[j] = 0.f;
    int kb = lane * 4;
    #pragma unroll
    for (int kk = 0; kk < 4; kk++) {
        float c = xk[kk];
        #pragma unroll
        for (int q = 0; q < 4; q++) {
            float4 wv = w1s[(kb + kk) * 4 + q];
            a[q * 4 + 0] += c * wv.x;
            a[q * 4 + 1] += c * wv.y;
            a[q * 4 + 2] += c * wv.z;
            a[q * 4 + 3] += c * wv.w;
        }
    }
    #pragma unroll
    for (int j = 0; j < 16; j++) {
        #pragma unroll
        for (int off = 16; off; off >>= 1)
            a[j] += __shfl_xor_sync(0xffffffffu, a[j], off);
    }
    if (lane == 0) {
        float dv = g_dinv[w];
        float4* o = (float4*)(g_h1 + (size_t)w * 16);
        o[0] = make_float4(a[0] * dv,  a[1] * dv,  a[2] * dv,  a[3] * dv);
        o[1] = make_float4(a[4] * dv,  a[5] * dv,  a[6] * dv,  a[7] * dv);
        o[2] = make_float4(a[8] * dv,  a[9] * dv,  a[10] * dv, a[11] * dv);
        o[3] = make_float4(a[12] * dv, a[13] * dv, a[14] * dv, a[15] * dv);
    }
}

// -------- 8: prop1: q[d] = relu(dinv[d]*(sum h1[s] + h1[d]) + b1) * dinv[d] --------
__global__ void prop1_kernel(const float* __restrict__ b1) {
    int w = (blockIdx.x * blockDim.x + threadIdx.x) >> 5;
    if (w >= NUM_N) return;
    int lane = threadIdx.x & 31;
    int dim = lane & 15, eo = lane >> 4;
    int start = g_off[w], dg = g_deg[w];
    float acc = 0.f;
    for (int e = eo; e < dg; e += 2) {
        int s = g_csrc[start + e];
        acc += g_h1[s * 16 + dim];
    }
    acc += __shfl_down_sync(0xffffffffu, acc, 16);
    if (lane < 16) {
        float dv = g_dinv[w];
        float v = dv * (acc + g_h1[w * 16 + dim]) + b1[dim];
        g_q[w * 16 + dim] = fmaxf(v, 0.f) * dv;
    }
}

// -------- 9: prop2 (16-dim!): r[d] = dinv[d]*(sum q[s] + q[d]) --------
__global__ void prop2_kernel() {
    int w = (blockIdx.x * blockDim.x + threadIdx.x) >> 5;
    if (w >= NUM_N) return;
    int lane = threadIdx.x & 31;
    int dim = lane & 15, eo = lane >> 4;
    int start = g_off[w], dg = g_deg[w];
    float acc = 0.f;
    for (int e = eo; e < dg; e += 2) {
        int s = g_csrc[start + e];
        acc += g_q[s * 16 + dim];
    }
    acc += __shfl_down_sync(0xffffffffu, acc, 16);
    if (lane < 16) {
        float dv = g_dinv[w];
        g_r[w * 16 + dim] = dv * (acc + g_q[w * 16 + dim]);
    }
}

// -------- 10: fused GEMM2 + mean pooling --------
// pooled[g][c] = mean over nodes n of graph g of relu(r[n] @ W2[:,c] + b2[c])
__global__ void pool_gemm2_kernel(const float* __restrict__ W2, const float* __restrict__ b2) {
    __shared__ float4 w2s[16 * 32];   // w2s[k*32 + c4]
    __shared__ float4 red[8 * 32];
    int t = threadIdx.x, lane = t & 31, wid = t >> 5;
    for (int i = t; i < 16 * 32; i += blockDim.x)
        w2s[i] = ((const float4*)W2)[i];
    __syncthreads();
    int g = blockIdx.x;
    int start = g_boff[g], cnt = g_pcnt[g];
    float4 bv = ((const float4*)b2)[lane];
    float4 sum = make_float4(0.f, 0.f, 0.f, 0.f);

    // software-prefetch one node ahead (hide the L2-gather latency)
    int i = wid;
    float rv_next = 0.f;
    if (i < cnt) {
        int n = g_bnode[start + i];
        rv_next = (lane < 16) ? g_r[n * 16 + lane] : 0.f;
    }
    for (; i < cnt; i += 8) {
        float rv = rv_next;
        int inext = i + 8;
        if (inext < cnt) {
            int n2 = g_bnode[start + inext];
            rv_next = (lane < 16) ? g_r[n2 * 16 + lane] : 0.f;
        }
        float4 acc = bv;
        #pragma unroll
        for (int k = 0; k < 16; k++) {
            float s = __shfl_sync(0xffffffffu, rv, k);
            float4 wv = w2s[k * 32 + lane];
            acc.x += s * wv.x; acc.y += s * wv.y;
            acc.z += s * wv.z; acc.w += s * wv.w;
        }
        sum.x += fmaxf(acc.x, 0.f);
        sum.y += fmaxf(acc.y, 0.f);
        sum.z += fmaxf(acc.z, 0.f);
        sum.w += fmaxf(acc.w, 0.f);
    }
    red[wid * 32 + lane] = sum;
    __syncthreads();
    if (wid == 0) {
        float4 tot = red[lane];
        #pragma unroll
        for (int ww = 1; ww < 8; ww++) {
            float4 v = red[ww * 32 + lane];
            tot.x += v.x; tot.y += v.y; tot.z += v.z; tot.w += v.w;
        }
        float inv = 1.f / fmaxf((float)cnt, 1.f);
        ((float4*)g_pool)[g * 32 + lane] =
            make_float4(tot.x * inv, tot.y * inv, tot.z * inv, tot.w * inv);
    }
}

// -------- 11: final MLP + log_softmax --------
__global__ void mlp_kernel(const float* __restrict__ LW1, const float* __restrict__ Lb1,
                           const float* __restrict__ LW2, const float* __restrict__ Lb2,
                           float* __restrict__ out) {
    __shared__ float ps[128];
    __shared__ float z1[128];
    __shared__ float z2[2];
    int g = blockIdx.x, j = threadIdx.x;
    ps[j] = g_pool[g * 128 + j];
    __syncthreads();
    float acc = Lb1[j];
    #pragma unroll 8
    for (int k = 0; k < 128; k++) acc += ps[k] * LW1[k * 128 + j];
    z1[j] = fmaxf(acc, 0.f);
    __syncthreads();
    if (j < 2) {
        float a = Lb2[j];
        for (int k = 0; k < 128; k++) a += z1[k] * LW2[k * 2 + j];
        z2[j] = a;
    }
    __syncthreads();
    if (j == 0) {
        float m = fmaxf(z2[0], z2[1]);
        float lse = m + logf(expf(z2[0] - m) + expf(z2[1] - m));
        out[g * 2 + 0] = z2[0] - lse;
        out[g * 2 + 1] = z2[1] - lse;
    }
}

// -------- launch --------
extern "C" void kernel_launch(void* const* d_in, const int* in_sizes, int n_in,
                              void* d_out, int out_size) {
    const float* x   = (const float*)d_in[0];
    const void*  ei  = d_in[1];
    const void*  bat = d_in[2];
    const float* W1  = (const float*)d_in[3];
    const float* b1  = (const float*)d_in[4];
    const float* W2  = (const float*)d_in[5];
    const float* b2  = (const float*)d_in[6];
    const float* LW1 = (const float*)d_in[7];
    const float* Lb1 = (const float*)d_in[8];
    const float* LW2 = (const float*)d_in[9];
    const float* Lb2 = (const float*)d_in[10];
    float* out = (float*)d_out;

    zero_kernel<<<(NUM_N + 255) / 256, 256>>>();
    detect_kernel<<<2, 1024>>>(ei);
    convert_kernel<<<(NUM_E + 255) / 256, 256>>>(ei, bat);
    dinv_kernel<<<(NUM_N + 255) / 256, 256>>>();
    scan1_kernel<<<SCAN_NB, SCAN_B>>>();
    scan2_kernel<<<1, 32>>>();
    scan3_kernel<<<SCAN_NB, SCAN_B>>>();
    escatter_kernel<<<(NUM_E + 255) / 256, 256>>>();
    bscan_kernel<<<1, 32>>>();
    bscatter_kernel<<<(NUM_N + 255) / 256, 256>>>();

    gemm1_kernel<<<(NUM_N + 7) / 8, 256>>>(x, W1);
    prop1_kernel<<<(NUM_N + 7) / 8, 256>>>(b1);
    prop2_kernel<<<(NUM_N + 7) / 8, 256>>>();
    pool_gemm2_kernel<<<NUM_G, 256>>>(W2, b2);
    mlp_kernel<<<NUM_G, 128>>>(LW1, Lb1, LW2, Lb2, out);
}

// round 2
// speedup vs baseline: 1.1857x; 1.1857x over previous
#include <cuda_runtime.h>
#include <cuda_bf16.h>
#include <math.h>

#define NUM_N 100000
#define NUM_E 1600000
#define NUM_G 128
#define D_IN 128
#define D_H1 16
#define D_H2 128

#define CONV_B ((NUM_E + 255) / 256)      // 6250 convert blocks
#define GEMM_B ((NUM_N + 7) / 8)          // 12500 gemm blocks (8 warps/block)
#define S1_NB  ((NUM_N + 4095) / 4096)    // 25 scan blocks

// -------- device scratch (no allocations allowed) --------
__device__ int   g_flag_bad = 0;          // set (idempotently) iff indices are int32
__device__ int   g_src[NUM_E];
__device__ int   g_dst[NUM_E];
__device__ int   g_batch[NUM_N];
__device__ int   g_deg[NUM_N];            // in-degree (excl self loop)
__device__ float g_dinv[NUM_N];
__device__ int   g_woff[NUM_N];           // CSR offsets; consumed by escatter
__device__ int   g_csrc[NUM_E];           // src ids grouped by dst
__device__ int   g_bsum[S1_NB + 8];
__device__ int   g_pcnt[NUM_G];           // nodes per graph
__device__ int   g_boff[NUM_G];           // batch CSR offsets; consumed by bscatter
__device__ int   g_bnode[NUM_N];          // node ids grouped by graph
__device__ float g_h1[NUM_N * D_H1];      // x @ W1 (no dinv)
__device__ float g_q [NUM_N * D_H1];      // relu(layer1) * dinv
__device__ float g_r [NUM_N * D_H1];      // aggregated layer2 input (16-dim)
__device__ float g_poolp[4 * NUM_G * D_H2];  // per-quarter pooling partials

// -------- 1: zero + int64/int32 detection --------
__global__ void zero_detect_kernel(const void* ei) {
    int i = blockIdx.x * blockDim.x + threadIdx.x;
    if (i < NUM_N) g_deg[i] = 0;
    if (i < NUM_G) g_pcnt[i] = 0;
    if (i < 2048) {
        long long v = ((const long long*)ei)[i];
        if (v < 0 || v >= (long long)NUM_N) atomicOr(&g_flag_bad, 1);
    }
}

// -------- 2: convert indices + histograms  ||  gemm1: h1 = x @ W1 --------
__global__ void convert_gemm1_kernel(const void* ei, const void* bat,
                                     const float* __restrict__ x,
                                     const float* __restrict__ W1) {
    __shared__ float4 w1s[D_IN * 4];
    int bid = blockIdx.x;
    if (bid < CONV_B) {
        // ---- convert role ----
        int i = bid * 256 + threadIdx.x;
        bool f64 = (g_flag_bad == 0);
        if (i < NUM_E) {
            int s, d;
            if (f64) {
                s = (int)((const long long*)ei)[i];
                d = (int)((const long long*)ei)[NUM_E + i];
            } else {
                s = ((const int*)ei)[i];
                d = ((const int*)ei)[NUM_E + i];
            }
            g_src[i] = s;
            g_dst[i] = d;
            atomicAdd(&g_deg[d], 1);
        }
        if (i < NUM_N) {
            int b = f64 ? (int)((const long long*)bat)[i] : ((const int*)bat)[i];
            g_batch[i] = b;
            atomicAdd(&g_pcnt[b], 1);
        }
    } else {
        // ---- gemm role: one warp per node ----
        int gb = bid - CONV_B;
        for (int i = threadIdx.x; i < D_IN * 4; i += 256)
            w1s[i] = ((const float4*)W1)[i];
        __syncthreads();
        int w = gb * 8 + (threadIdx.x >> 5);
        if (w >= NUM_N) return;
        int lane = threadIdx.x & 31;
        float4 xv = ((const float4*)x)[(size_t)w * 32 + lane];  // k = 4*lane..4*lane+3
        float a[16];
        #pragma unroll
        for (int j = 0; j < 16; j++) a[j] = 0.f;
        {
            float xs[4] = {xv.x, xv.y, xv.z, xv.w};
            int kb4 = lane * 16;
            #pragma unroll
            for (int kk = 0; kk < 4; kk++) {
                float c = xs[kk];
                #pragma unroll
                for (int q = 0; q < 4; q++) {
                    float4 wv = w1s[kb4 + kk * 4 + q];
                    a[q * 4 + 0] = fmaf(c, wv.x, a[q * 4 + 0]);
                    a[q * 4 + 1] = fmaf(c, wv.y, a[q * 4 + 1]);
                    a[q * 4 + 2] = fmaf(c, wv.z, a[q * 4 + 2]);
                    a[q * 4 + 3] = fmaf(c, wv.w, a[q * 4 + 3]);
                }
            }
        }
        // halving butterfly reduction: 16 outputs over 32 lanes, 31 shfls
        {
            float t[16];
            #pragma unroll
            for (int i = 0; i < 16; i++) t[i] = __shfl_xor_sync(0xffffffffu, a[i], 16);
            if ((lane & 16) == 0) {
                #pragma unroll
                for (int i = 0; i < 8; i++) a[i] += t[i];
            } else {
                #pragma unroll
                for (int i = 0; i < 8; i++) a[i] = a[i + 8] + t[i + 8];
            }
        }
        {
            float t[8];
            #pragma unroll
            for (int i = 0; i < 8; i++) t[i] = __shfl_xor_sync(0xffffffffu, a[i], 8);
            if ((lane & 8) == 0) {
                #pragma unroll
                for (int i = 0; i < 4; i++) a[i] += t[i];
            } else {
                #pragma unroll
                for (int i = 0; i < 4; i++) a[i] = a[i + 4] + t[i + 4];
            }
        }
        {
            float t[4];
            #pragma unroll
            for (int i = 0; i < 4; i++) t[i] = __shfl_xor_sync(0xffffffffu, a[i], 4);
            if ((lane & 4) == 0) { a[0] += t[0]; a[1] += t[1]; }
            else                 { a[0] = a[2] + t[2]; a[1] = a[3] + t[3]; }
        }
        {
            float t0 = __shfl_xor_sync(0xffffffffu, a[0], 2);
            float t1 = __shfl_xor_sync(0xffffffffu, a[1], 2);
            if ((lane & 2) == 0) a[0] += t0; else a[0] = a[1] + t1;
        }
        a[0] += __shfl_xor_sync(0xffffffffu, a[0], 1);
        if ((lane & 1) == 0)
            g_h1[(size_t)w * 16 + (lane >> 1)] = a[0];
    }
}

// -------- 3: block-local exclusive scan of deg (+dinv) --------
__global__ void scan1_kernel() {
    __shared__ int wsum[32];
    int t = threadIdx.x, lane = t & 31, wid = t >> 5;
    int base = blockIdx.x * 4096 + t * 4;
    int4 d = make_int4(0, 0, 0, 0);
    if (base + 3 < NUM_N) d = *(const int4*)(g_deg + base);
    else if (base < NUM_N) {
        d.x = g_deg[base];
        if (base + 1 < NUM_N) d.y = g_deg[base + 1];
        if (base + 2 < NUM_N) d.z = g_deg[base + 2];
    }
    int s1 = d.x + d.y, s2 = s1 + d.z, s3 = s2 + d.w;
    int v = s3;
    #pragma unroll
    for (int o = 1; o < 32; o <<= 1) {
        int n = __shfl_up_sync(0xffffffffu, v, o);
        if (lane >= o) v += n;
    }
    if (lane == 31) wsum[wid] = v;
    __syncthreads();
    if (wid == 0) {
        int wv = wsum[lane];
        #pragma unroll
        for (int o = 1; o < 32; o <<= 1) {
            int n = __shfl_up_sync(0xffffffffu, wv, o);
            if (lane >= o) wv += n;
        }
        wsum[lane] = wv;
    }
    __syncthreads();
    int ebase = (wid ? wsum[wid - 1] : 0) + v - s3;
    if (base + 3 < NUM_N) {
        *(int4*)(g_woff + base) = make_int4(ebase, ebase + d.x, ebase + s1, ebase + s2);
        *(float4*)(g_dinv + base) = make_float4(
            rsqrtf((float)d.x + 1.f), rsqrtf((float)d.y + 1.f),
            rsqrtf((float)d.z + 1.f), rsqrtf((float)d.w + 1.f));
    } else if (base < NUM_N) {
        g_woff[base] = ebase;           g_dinv[base] = rsqrtf((float)d.x + 1.f);
        if (base + 1 < NUM_N) { g_woff[base + 1] = ebase + d.x; g_dinv[base + 1] = rsqrtf((float)d.y + 1.f); }
        if (base + 2 < NUM_N) { g_woff[base + 2] = ebase + s1;  g_dinv[base + 2] = rsqrtf((float)d.z + 1.f); }
    }
    if (t == 1023) g_bsum[blockIdx.x] = wsum[31];
}

// -------- 4: parallel scan of block sums (25) + batch counts (128) --------
__global__ void scan2p_kernel() {
    __shared__ int sA[128], sB[128];
    int t = threadIdx.x;
    int a = (t < S1_NB) ? g_bsum[t] : 0;
    int b = g_pcnt[t];
    sA[t] = a; sB[t] = b;
    __syncthreads();
    for (int o = 1; o < 128; o <<= 1) {
        int xa = (t >= o) ? sA[t - o] : 0;
        int xb = (t >= o) ? sB[t - o] : 0;
        __syncthreads();
        sA[t] += xa; sB[t] += xb;
        __syncthreads();
    }
    if (t < S1_NB) g_bsum[t] = sA[t] - a;   // exclusive block bases
    g_boff[t] = sB[t] - b;                   // exclusive graph bases
}

// -------- 5: add block bases --------
__global__ void scan3_kernel() {
    int t = threadIdx.x;
    int base = blockIdx.x * 4096 + t * 4;
    int add = g_bsum[blockIdx.x];
    if (base + 3 < NUM_N) {
        int4 v = *(int4*)(g_woff + base);
        v.x += add; v.y += add; v.z += add; v.w += add;
        *(int4*)(g_woff + base) = v;
    } else if (base < NUM_N) {
        g_woff[base] += add;
        if (base + 1 < NUM_N) g_woff[base + 1] += add;
        if (base + 2 < NUM_N) g_woff[base + 2] += add;
    }
}

// -------- 6: scatter edges into dst-CSR (consumes g_woff) --------
__global__ void escatter_kernel() {
    int i = blockIdx.x * blockDim.x + threadIdx.x;
    if (i < NUM_E) {
        int d = g_dst[i];
        int pos = atomicAdd(&g_woff[d], 1);
        g_csrc[pos] = g_src[i];
    }
}

// -------- 7: batch scatter (consumes g_boff) --------
__global__ void bscatter_kernel() {
    int i = blockIdx.x * blockDim.x + threadIdx.x;
    if (i < NUM_N) {
        int b = g_batch[i];
        int pos = atomicAdd(&g_boff[b], 1);
        g_bnode[pos] = i;
    }
}

// -------- 8: prop1: q = relu(dinv_d*(sum dinv_s*h1[s] + dinv_d*h1[d]) + b1) * dinv_d
__global__ void prop1_kernel(const float* __restrict__ b1) {
    int w = (blockIdx.x * blockDim.x + threadIdx.x) >> 5;
    if (w >= NUM_N) return;
    int lane = threadIdx.x & 31;
    int sub = lane & 3, grp = lane >> 2;       // 8 edges/iter, float4 per edge
    int dg = g_deg[w];
    int start = g_woff[w] - dg;
    float ax = 0.f, ay = 0.f, az = 0.f, aw = 0.f;
    for (int e = grp; e < dg; e += 8) {
        int s = g_csrc[start + e];
        float dv = g_dinv[s];
        float4 v = ((const float4*)g_h1)[s * 4 + sub];
        ax = fmaf(dv, v.x, ax); ay = fmaf(dv, v.y, ay);
        az = fmaf(dv, v.z, az); aw = fmaf(dv, v.w, aw);
    }
    #pragma unroll
    for (int o = 4; o < 32; o <<= 1) {
        ax += __shfl_xor_sync(0xffffffffu, ax, o);
        ay += __shfl_xor_sync(0xffffffffu, ay, o);
        az += __shfl_xor_sync(0xffffffffu, az, o);
        aw += __shfl_xor_sync(0xffffffffu, aw, o);
    }
    if (lane < 4) {
        float dvd = g_dinv[w];
        float4 hs = ((const float4*)g_h1)[w * 4 + sub];
        float4 bv = ((const float4*)b1)[sub];
        float4 o;
        o.x = fmaxf(fmaf(dvd, ax + dvd * hs.x, bv.x), 0.f) * dvd;
        o.y = fmaxf(fmaf(dvd, ay + dvd * hs.y, bv.y), 0.f) * dvd;
        o.z = fmaxf(fmaf(dvd, az + dvd * hs.z, bv.z), 0.f) * dvd;
        o.w = fmaxf(fmaf(dvd, aw + dvd * hs.w, bv.w), 0.f) * dvd;
        ((float4*)g_q)[w * 4 + sub] = o;
    }
}

// -------- 9: prop2: r = dinv_d * (sum q[s] + q[d])  (16-dim) --------
__global__ void prop2_kernel() {
    int w = (blockIdx.x * blockDim.x + threadIdx.x) >> 5;
    if (w >= NUM_N) return;
    int lane = threadIdx.x & 31;
    int sub = lane & 3, grp = lane >> 2;
    int dg = g_deg[w];
    int start = g_woff[w] - dg;
    float ax = 0.f, ay = 0.f, az = 0.f, aw = 0.f;
    for (int e = grp; e < dg; e += 8) {
        int s = g_csrc[start + e];
        float4 v = ((const float4*)g_q)[s * 4 + sub];
        ax += v.x; ay += v.y; az += v.z; aw += v.w;
    }
    #pragma unroll
    for (int o = 4; o < 32; o <<= 1) {
        ax += __shfl_xor_sync(0xffffffffu, ax, o);
        ay += __shfl_xor_sync(0xffffffffu, ay, o);
        az += __shfl_xor_sync(0xffffffffu, az, o);
        aw += __shfl_xor_sync(0xffffffffu, aw, o);
    }
    if (lane < 4) {
        float dvd = g_dinv[w];
        float4 qs = ((const float4*)g_q)[w * 4 + sub];
        float4 o;
        o.x = dvd * (ax + qs.x); o.y = dvd * (ay + qs.y);
        o.z = dvd * (az + qs.z); o.w = dvd * (aw + qs.w);
        ((float4*)g_r)[w * 4 + sub] = o;
    }
}

// -------- 10: fused GEMM2 + mean pooling (4 blocks/graph, deterministic partials)
__global__ void pool_gemm2_kernel(const float* __restrict__ W2, const float* __restrict__ b2) {
    __shared__ float4 w2s[16 * 32];
    __shared__ float4 red[8 * 32];
    int t = threadIdx.x, lane = t & 31, wid = t >> 5;
    for (int i = t; i < 16 * 32; i += 256)
        w2s[i] = ((const float4*)W2)[i];
    __syncthreads();
    int g = blockIdx.x >> 2, qt = blockIdx.x & 3;
    int cnt = g_pcnt[g];
    int start = g_boff[g] - cnt;
    float4 bv = ((const float4*)b2)[lane];
    float4 sum = make_float4(0.f, 0.f, 0.f, 0.f);
    for (int i = qt * 8 + wid; i < cnt; i += 32) {
        int n = g_bnode[start + i];
        float rv = (lane < 16) ? g_r[n * 16 + lane] : 0.f;
        float4 acc = bv;
        #pragma unroll
        for (int k = 0; k < 16; k++) {
            float s = __shfl_sync(0xffffffffu, rv, k);
            float4 wv = w2s[k * 32 + lane];
            acc.x = fmaf(s, wv.x, acc.x); acc.y = fmaf(s, wv.y, acc.y);
            acc.z = fmaf(s, wv.z, acc.z); acc.w = fmaf(s, wv.w, acc.w);
        }
        sum.x += fmaxf(acc.x, 0.f); sum.y += fmaxf(acc.y, 0.f);
        sum.z += fmaxf(acc.z, 0.f); sum.w += fmaxf(acc.w, 0.f);
    }
    red[wid * 32 + lane] = sum;
    __syncthreads();
    if (wid == 0) {
        float4 tot = red[lane];
        #pragma unroll
        for (int ww = 1; ww < 8; ww++) {
            float4 v = red[ww * 32 + lane];
            tot.x += v.x; tot.y += v.y; tot.z += v.z; tot.w += v.w;
        }
        ((float4*)g_poolp)[(qt * NUM_G + g) * 32 + lane] = tot;
    }
}

// -------- 11: final MLP + log_softmax --------
__global__ void mlp_kernel(const float* __restrict__ LW1, const float* __restrict__ Lb1,
                           const float* __restrict__ LW2, const float* __restrict__ Lb2,
                           float* __restrict__ out) {
    __shared__ float ps[128];
    __shared__ float z1[128];
    __shared__ float z2[2];
    int g = blockIdx.x, j = threadIdx.x;
    float inv = 1.f / fmaxf((float)g_pcnt[g], 1.f);
    ps[j] = (g_poolp[0 * NUM_G * 128 + g * 128 + j] +
             g_poolp[1 * NUM_G * 128 + g * 128 + j] +
             g_poolp[2 * NUM_G * 128 + g * 128 + j] +
             g_poolp[3 * NUM_G * 128 + g * 128 + j]) * inv;
    __syncthreads();
    float acc = Lb1[j];
    #pragma unroll 8
    for (int k = 0; k < 128; k++) acc = fmaf(ps[k], LW1[k * 128 + j], acc);
    z1[j] = fmaxf(acc, 0.f);
    __syncthreads();
    if (j < 2) {
        float a = Lb2[j];
        for (int k = 0; k < 128; k++) a = fmaf(z1[k], LW2[k * 2 + j], a);
        z2[j] = a;
    }
    __syncthreads();
    if (j == 0) {
        float m = fmaxf(z2[0], z2[1]);
        float lse = m + logf(expf(z2[0] - m) + expf(z2[1] - m));
        out[g * 2 + 0] = z2[0] - lse;
        out[g * 2 + 1] = z2[1] - lse;
    }
}

// -------- launch --------
extern "C" void kernel_launch(void* const* d_in, const int* in_sizes, int n_in,
                              void* d_out, int out_size) {
    const float* x   = (const float*)d_in[0];
    const void*  ei  = d_in[1];
    const void*  bat = d_in[2];
    const float* W1  = (const float*)d_in[3];
    const float* b1  = (const float*)d_in[4];
    const float* W2  = (const float*)d_in[5];
    const float* b2  = (const float*)d_in[6];
    const float* LW1 = (const float*)d_in[7];
    const float* Lb1 = (const float*)d_in[8];
    const float* LW2 = (const float*)d_in[9];
    const float* Lb2 = (const float*)d_in[10];
    float* out = (float*)d_out;

    zero_detect_kernel<<<(NUM_N + 255) / 256, 256>>>(ei);
    convert_gemm1_kernel<<<CONV_B + GEMM_B, 256>>>(ei, bat, x, W1);
    scan1_kernel<<<S1_NB, 1024>>>();
    scan2p_kernel<<<1, 128>>>();
    scan3_kernel<<<S1_NB, 1024>>>();
    escatter_kernel<<<(NUM_E + 255) / 256, 256>>>();
    bscatter_kernel<<<(NUM_N + 255) / 256, 256>>>();
    prop1_kernel<<<(NUM_N + 7) / 8, 256>>>(b1);
    prop2_kernel<<<(NUM_N + 7) / 8, 256>>>();
    pool_gemm2_kernel<<<4 * NUM_G, 256>>>(W2, b2);
    mlp_kernel<<<NUM_G, 128>>>(LW1, Lb1, LW2, Lb2, out);
}

// round 3
// speedup vs baseline: 1.1992x; 1.0114x over previous
#include <cuda_runtime.h>
#include <cuda_bf16.h>
#include <math.h>

#define NUM_N 100000
#define NUM_E 1600000
#define NUM_G 128
#define D_IN 128
#define D_H1 16
#define D_H2 128

#define CONV_B ((NUM_E + 255) / 256)      // 6250 histogram blocks
#define GEMM_B ((NUM_N + 7) / 8)          // 12500 gemm blocks (8 warps/block)
#define S1_NB  ((NUM_N + 4095) / 4096)    // 25 scan blocks
#define EB     ((NUM_E + 255) / 256)      // edge-scatter blocks
#define NB     ((NUM_N + 255) / 256)      // node blocks

// -------- device scratch (no allocations allowed) --------
__device__ int   g_flag_bad = 0;          // set (idempotently) iff indices are int32
__device__ int   g_batch[NUM_N];
__device__ int   g_deg[NUM_N];            // in-degree (excl self loop)
__device__ float g_dinv[NUM_N];
__device__ int   g_woff[NUM_N];           // CSR offsets; consumed by scatter
__device__ int   g_csrc[NUM_E];           // src ids grouped by dst
__device__ volatile int g_scanflag[S1_NB];
__device__ int   g_pcnt[NUM_G];           // nodes per graph
__device__ int   g_boff[NUM_G];           // batch CSR offsets; consumed by scatter
__device__ int   g_bnode[NUM_N];          // node ids grouped by graph
__device__ float g_h1[NUM_N * D_H1];      // x @ W1, later pre-scaled by dinv
__device__ float g_q [NUM_N * D_H1];      // relu(layer1) * dinv
__device__ float g_r [NUM_N * D_H1];      // aggregated layer2 input (16-dim)
__device__ float g_poolp[4 * NUM_G * D_H2];  // per-quarter pooling partials

// -------- 1: zero + int64/int32 detection --------
__global__ void zero_detect_kernel(const void* ei) {
    int i = blockIdx.x * blockDim.x + threadIdx.x;
    if (i < NUM_N) g_deg[i] = 0;
    if (i < NUM_G) g_pcnt[i] = 0;
    if (i < S1_NB) g_scanflag[i] = 0;
    if (i < 2048) {
        long long v = ((const long long*)ei)[i];
        if (v < 0 || v >= (long long)NUM_N) atomicOr(&g_flag_bad, 1);
    }
}

// -------- 2: histograms (dst-degree, batch)  ||  gemm1: h1 = x @ W1 --------
__global__ void convert_gemm1_kernel(const void* ei, const void* bat,
                                     const float* __restrict__ x,
                                     const float* __restrict__ W1) {
    __shared__ float4 w1s[D_IN * 4];
    int bid = blockIdx.x;
    if (bid < CONV_B) {
        int i = bid * 256 + threadIdx.x;
        bool f64 = (g_flag_bad == 0);
        if (i < NUM_E) {
            int d = f64 ? (int)((const long long*)ei)[NUM_E + i]
                        : ((const int*)ei)[NUM_E + i];
            atomicAdd(&g_deg[d], 1);
        }
        if (i < NUM_N) {
            int b = f64 ? (int)((const long long*)bat)[i] : ((const int*)bat)[i];
            g_batch[i] = b;
            atomicAdd(&g_pcnt[b], 1);
        }
    } else {
        // ---- gemm role: one warp per node ----
        int gb = bid - CONV_B;
        for (int i = threadIdx.x; i < D_IN * 4; i += 256)
            w1s[i] = ((const float4*)W1)[i];
        __syncthreads();
        int w = gb * 8 + (threadIdx.x >> 5);
        if (w >= NUM_N) return;
        int lane = threadIdx.x & 31;
        float4 xv = ((const float4*)x)[(size_t)w * 32 + lane];
        float a[16];
        #pragma unroll
        for (int j = 0; j < 16; j++) a[j] = 0.f;
        {
            float xs[4] = {xv.x, xv.y, xv.z, xv.w};
            int kb4 = lane * 16;
            #pragma unroll
            for (int kk = 0; kk < 4; kk++) {
                float c = xs[kk];
                #pragma unroll
                for (int q = 0; q < 4; q++) {
                    float4 wv = w1s[kb4 + kk * 4 + q];
                    a[q * 4 + 0] = fmaf(c, wv.x, a[q * 4 + 0]);
                    a[q * 4 + 1] = fmaf(c, wv.y, a[q * 4 + 1]);
                    a[q * 4 + 2] = fmaf(c, wv.z, a[q * 4 + 2]);
                    a[q * 4 + 3] = fmaf(c, wv.w, a[q * 4 + 3]);
                }
            }
        }
        // halving butterfly reduction: 16 outputs, 31 shfls
        {
            float t[16];
            #pragma unroll
            for (int i = 0; i < 16; i++) t[i] = __shfl_xor_sync(0xffffffffu, a[i], 16);
            if ((lane & 16) == 0) {
                #pragma unroll
                for (int i = 0; i < 8; i++) a[i] += t[i];
            } else {
                #pragma unroll
                for (int i = 0; i < 8; i++) a[i] = a[i + 8] + t[i + 8];
            }
        }
        {
            float t[8];
            #pragma unroll
            for (int i = 0; i < 8; i++) t[i] = __shfl_xor_sync(0xffffffffu, a[i], 8);
            if ((lane & 8) == 0) {
                #pragma unroll
                for (int i = 0; i < 4; i++) a[i] += t[i];
            } else {
                #pragma unroll
                for (int i = 0; i < 4; i++) a[i] = a[i + 4] + t[i + 4];
            }
        }
        {
            float t[4];
            #pragma unroll
            for (int i = 0; i < 4; i++) t[i] = __shfl_xor_sync(0xffffffffu, a[i], 4);
            if ((lane & 4) == 0) { a[0] += t[0]; a[1] += t[1]; }
            else                 { a[0] = a[2] + t[2]; a[1] = a[3] + t[3]; }
        }
        {
            float t0 = __shfl_xor_sync(0xffffffffu, a[0], 2);
            float t1 = __shfl_xor_sync(0xffffffffu, a[1], 2);
            if ((lane & 2) == 0) a[0] += t0; else a[0] = a[1] + t1;
        }
        a[0] += __shfl_xor_sync(0xffffffffu, a[0], 1);
        if ((lane & 1) == 0)
            g_h1[(size_t)w * 16 + (lane >> 1)] = a[0];
    }
}

// -------- 3: single-kernel exclusive scan (decoupled lookback) + dinv + batch scan
__global__ void scan_kernel() {
    __shared__ int wsum[32];
    __shared__ int sbase;
    int t = threadIdx.x, lane = t & 31, wid = t >> 5;
    int base = blockIdx.x * 4096 + t * 4;
    int4 d = make_int4(0, 0, 0, 0);
    if (base + 3 < NUM_N) d = *(const int4*)(g_deg + base);
    else if (base < NUM_N) {
        d.x = g_deg[base];
        if (base + 1 < NUM_N) d.y = g_deg[base + 1];
        if (base + 2 < NUM_N) d.z = g_deg[base + 2];
    }
    int s1 = d.x + d.y, s2 = s1 + d.z, s3 = s2 + d.w;
    int v = s3;
    #pragma unroll
    for (int o = 1; o < 32; o <<= 1) {
        int n = __shfl_up_sync(0xffffffffu, v, o);
        if (lane >= o) v += n;
    }
    if (lane == 31) wsum[wid] = v;
    __syncthreads();
    if (wid == 0) {
        int wv = wsum[lane];
        #pragma unroll
        for (int o = 1; o < 32; o <<= 1) {
            int n = __shfl_up_sync(0xffffffffu, wv, o);
            if (lane >= o) wv += n;
        }
        wsum[lane] = wv;
    }
    __syncthreads();
    // lookback chain (all 25 blocks co-resident: safe)
    if (t == 0) {
        int ex = 0;
        if (blockIdx.x > 0) {
            int f;
            while ((f = g_scanflag[blockIdx.x - 1]) == 0) { }
            ex = f - 1;
        }
        g_scanflag[blockIdx.x] = ex + wsum[31] + 1;
        sbase = ex;
    }
    // batch-count scan in warp 1 of block 0 (g_pcnt ready since prior kernel)
    if (blockIdx.x == 0 && wid == 1) {
        int p0 = g_pcnt[lane * 4], p1 = g_pcnt[lane * 4 + 1];
        int p2 = g_pcnt[lane * 4 + 2], p3 = g_pcnt[lane * 4 + 3];
        int t1 = p0 + p1, t2 = t1 + p2, t3 = t2 + p3;
        int vv = t3;
        #pragma unroll
        for (int o = 1; o < 32; o <<= 1) {
            int n = __shfl_up_sync(0xffffffffu, vv, o);
            if (lane >= o) vv += n;
        }
        int exb = vv - t3;
        g_boff[lane * 4 + 0] = exb;
        g_boff[lane * 4 + 1] = exb + p0;
        g_boff[lane * 4 + 2] = exb + t1;
        g_boff[lane * 4 + 3] = exb + t2;
    }
    __syncthreads();
    int ebase = sbase + (wid ? wsum[wid - 1] : 0) + v - s3;
    if (base + 3 < NUM_N) {
        *(int4*)(g_woff + base) = make_int4(ebase, ebase + d.x, ebase + s1, ebase + s2);
        *(float4*)(g_dinv + base) = make_float4(
            rsqrtf((float)d.x + 1.f), rsqrtf((float)d.y + 1.f),
            rsqrtf((float)d.z + 1.f), rsqrtf((float)d.w + 1.f));
    } else if (base < NUM_N) {
        g_woff[base] = ebase;           g_dinv[base] = rsqrtf((float)d.x + 1.f);
        if (base + 1 < NUM_N) { g_woff[base + 1] = ebase + d.x; g_dinv[base + 1] = rsqrtf((float)d.y + 1.f); }
        if (base + 2 < NUM_N) { g_woff[base + 2] = ebase + s1;  g_dinv[base + 2] = rsqrtf((float)d.z + 1.f); }
    }
}

// -------- 4: scatter edges + scatter batch + prescale h1 by dinv (role split)
__global__ void scatter_kernel(const void* ei) {
    int bid = blockIdx.x;
    if (bid < EB) {
        int i = bid * 256 + threadIdx.x;
        bool f64 = (g_flag_bad == 0);
        if (i < NUM_E) {
            int s, d;
            if (f64) {
                s = (int)((const long long*)ei)[i];
                d = (int)((const long long*)ei)[NUM_E + i];
            } else {
                s = ((const int*)ei)[i];
                d = ((const int*)ei)[NUM_E + i];
            }
            int pos = atomicAdd(&g_woff[d], 1);
            g_csrc[pos] = s;
        }
    } else if (bid < EB + NB) {
        int i = (bid - EB) * 256 + threadIdx.x;
        if (i < NUM_N) {
            int b = g_batch[i];
            int pos = atomicAdd(&g_boff[b], 1);
            g_bnode[pos] = i;
        }
    } else {
        // prescale h1 rows by dinv: one warp per 8 nodes (4 lanes/node)
        int i = (bid - EB - NB) * 256 + threadIdx.x;   // float4 index
        int n = i >> 2;
        if (n < NUM_N) {
            float dv = g_dinv[n];
            float4 v = ((float4*)g_h1)[i];
            v.x *= dv; v.y *= dv; v.z *= dv; v.w *= dv;
            ((float4*)g_h1)[i] = v;
        }
    }
}

// -------- 5: prop1: q = relu(dinv_d*(sum h1s[s] + h1s[d]) + b1) * dinv_d
//   (h1s already pre-scaled by dinv)
__global__ void prop1_kernel(const float* __restrict__ b1) {
    int w = (blockIdx.x * blockDim.x + threadIdx.x) >> 5;
    if (w >= NUM_N) return;
    int lane = threadIdx.x & 31;
    int sub = lane & 3, grp = lane >> 2;       // 8 edges/iter, float4 per edge
    int dg = g_deg[w];
    int start = g_woff[w] - dg;
    float ax = 0.f, ay = 0.f, az = 0.f, aw = 0.f;
    for (int e = grp; e < dg; e += 8) {
        int s = g_csrc[start + e];
        float4 v = ((const float4*)g_h1)[s * 4 + sub];
        ax += v.x; ay += v.y; az += v.z; aw += v.w;
    }
    #pragma unroll
    for (int o = 4; o < 32; o <<= 1) {
        ax += __shfl_xor_sync(0xffffffffu, ax, o);
        ay += __shfl_xor_sync(0xffffffffu, ay, o);
        az += __shfl_xor_sync(0xffffffffu, az, o);
        aw += __shfl_xor_sync(0xffffffffu, aw, o);
    }
    if (lane < 4) {
        float dvd = g_dinv[w];
        float4 hs = ((const float4*)g_h1)[w * 4 + sub];
        float4 bv = ((const float4*)b1)[sub];
        float4 o;
        o.x = fmaxf(fmaf(dvd, ax + hs.x, bv.x), 0.f) * dvd;
        o.y = fmaxf(fmaf(dvd, ay + hs.y, bv.y), 0.f) * dvd;
        o.z = fmaxf(fmaf(dvd, az + hs.z, bv.z), 0.f) * dvd;
        o.w = fmaxf(fmaf(dvd, aw + hs.w, bv.w), 0.f) * dvd;
        ((float4*)g_q)[w * 4 + sub] = o;
    }
}

// -------- 6: prop2: r = dinv_d * (sum q[s] + q[d])  (16-dim) --------
__global__ void prop2_kernel() {
    int w = (blockIdx.x * blockDim.x + threadIdx.x) >> 5;
    if (w >= NUM_N) return;
    int lane = threadIdx.x & 31;
    int sub = lane & 3, grp = lane >> 2;
    int dg = g_deg[w];
    int start = g_woff[w] - dg;
    float ax = 0.f, ay = 0.f, az = 0.f, aw = 0.f;
    for (int e = grp; e < dg; e += 8) {
        int s = g_csrc[start + e];
        float4 v = ((const float4*)g_q)[s * 4 + sub];
        ax += v.x; ay += v.y; az += v.z; aw += v.w;
    }
    #pragma unroll
    for (int o = 4; o < 32; o <<= 1) {
        ax += __shfl_xor_sync(0xffffffffu, ax, o);
        ay += __shfl_xor_sync(0xffffffffu, ay, o);
        az += __shfl_xor_sync(0xffffffffu, az, o);
        aw += __shfl_xor_sync(0xffffffffu, aw, o);
    }
    if (lane < 4) {
        float dvd = g_dinv[w];
        float4 qs = ((const float4*)g_q)[w * 4 + sub];
        float4 o;
        o.x = dvd * (ax + qs.x); o.y = dvd * (ay + qs.y);
        o.z = dvd * (az + qs.z); o.w = dvd * (aw + qs.w);
        ((float4*)g_r)[w * 4 + sub] = o;
    }
}

// -------- 7: fused GEMM2 + mean pooling (4 blocks/graph, deterministic partials)
__global__ void pool_gemm2_kernel(const float* __restrict__ W2, const float* __restrict__ b2) {
    __shared__ float4 w2s[16 * 32];
    __shared__ float4 red[8 * 32];
    int t = threadIdx.x, lane = t & 31, wid = t >> 5;
    for (int i = t; i < 16 * 32; i += 256)
        w2s[i] = ((const float4*)W2)[i];
    __syncthreads();
    int g = blockIdx.x >> 2, qt = blockIdx.x & 3;
    int cnt = g_pcnt[g];
    int start = g_boff[g] - cnt;
    float4 bv = ((const float4*)b2)[lane];
    float4 sum = make_float4(0.f, 0.f, 0.f, 0.f);
    for (int i = qt * 8 + wid; i < cnt; i += 32) {
        int n = g_bnode[start + i];
        float rv = (lane < 16) ? g_r[n * 16 + lane] : 0.f;
        float4 acc = bv;
        #pragma unroll
        for (int k = 0; k < 16; k++) {
            float s = __shfl_sync(0xffffffffu, rv, k);
            float4 wv = w2s[k * 32 + lane];
            acc.x = fmaf(s, wv.x, acc.x); acc.y = fmaf(s, wv.y, acc.y);
            acc.z = fmaf(s, wv.z, acc.z); acc.w = fmaf(s, wv.w, acc.w);
        }
        sum.x += fmaxf(acc.x, 0.f); sum.y += fmaxf(acc.y, 0.f);
        sum.z += fmaxf(acc.z, 0.f); sum.w += fmaxf(acc.w, 0.f);
    }
    red[wid * 32 + lane] = sum;
    __syncthreads();
    if (wid == 0) {
        float4 tot = red[lane];
        #pragma unroll
        for (int ww = 1; ww < 8; ww++) {
            float4 v = red[ww * 32 + lane];
            tot.x += v.x; tot.y += v.y; tot.z += v.z; tot.w += v.w;
        }
        ((float4*)g_poolp)[(qt * NUM_G + g) * 32 + lane] = tot;
    }
}

// -------- 8: final MLP + log_softmax --------
__global__ void mlp_kernel(const float* __restrict__ LW1, const float* __restrict__ Lb1,
                           const float* __restrict__ LW2, const float* __restrict__ Lb2,
                           float* __restrict__ out) {
    __shared__ float ps[128];
    __shared__ float z1[128];
    __shared__ float z2[2];
    int g = blockIdx.x, j = threadIdx.x;
    float inv = 1.f / fmaxf((float)g_pcnt[g], 1.f);
    ps[j] = (g_poolp[0 * NUM_G * 128 + g * 128 + j] +
             g_poolp[1 * NUM_G * 128 + g * 128 + j] +
             g_poolp[2 * NUM_G * 128 + g * 128 + j] +
             g_poolp[3 * NUM_G * 128 + g * 128 + j]) * inv;
    __syncthreads();
    float acc = Lb1[j];
    #pragma unroll 8
    for (int k = 0; k < 128; k++) acc = fmaf(ps[k], LW1[k * 128 + j], acc);
    z1[j] = fmaxf(acc, 0.f);
    __syncthreads();
    if (j < 2) {
        float a = Lb2[j];
        for (int k = 0; k < 128; k++) a = fmaf(z1[k], LW2[k * 2 + j], a);
        z2[j] = a;
    }
    __syncthreads();
    if (j == 0) {
        float m = fmaxf(z2[0], z2[1]);
        float lse = m + logf(expf(z2[0] - m) + expf(z2[1] - m));
        out[g * 2 + 0] = z2[0] - lse;
        out[g * 2 + 1] = z2[1] - lse;
    }
}

// -------- launch --------
extern "C" void kernel_launch(void* const* d_in, const int* in_sizes, int n_in,
                              void* d_out, int out_size) {
    const float* x   = (const float*)d_in[0];
    const void*  ei  = d_in[1];
    const void*  bat = d_in[2];
    const float* W1  = (const float*)d_in[3];
    const float* b1  = (const float*)d_in[4];
    const float* W2  = (const float*)d_in[5];
    const float* b2  = (const float*)d_in[6];
    const float* LW1 = (const float*)d_in[7];
    const float* Lb1 = (const float*)d_in[8];
    const float* LW2 = (const float*)d_in[9];
    const float* Lb2 = (const float*)d_in[10];
    float* out = (float*)d_out;

    const int SCALE_B = (NUM_N * 4 + 255) / 256;   // h1 prescale blocks

    zero_detect_kernel<<<(NUM_N + 255) / 256, 256>>>(ei);
    convert_gemm1_kernel<<<CONV_B + GEMM_B, 256>>>(ei, bat, x, W1);
    scan_kernel<<<S1_NB, 1024>>>();
    scatter_kernel<<<EB + NB + SCALE_B, 256>>>(ei);
    prop1_kernel<<<(NUM_N + 7) / 8, 256>>>(b1);
    prop2_kernel<<<(NUM_N + 7) / 8, 256>>>();
    pool_gemm2_kernel<<<4 * NUM_G, 256>>>(W2, b2);
    mlp_kernel<<<NUM_G, 128>>>(LW1, Lb1, LW2, Lb2, out);
}

// round 4
// speedup vs baseline: 1.6872x; 1.4069x over previous
#include <cuda_runtime.h>
#include <cuda_bf16.h>
#include <math.h>

#define NUM_N 100000
#define NUM_E 1600000
#define NUM_G 128
#define D_IN 128

#define GRID  148
#define TPB   1024
#define GT    (GRID * TPB)        // 151552 threads
#define NWARP (GT / 32)           // 4736 warps
#define CHUNK 676                 // 148*676 = 100048 >= NUM_N

// -------- device scratch (no allocations allowed; statics start zeroed) ----
__device__ int   g_bar[8];           // grid-barrier slots (cyclic reset)
__device__ int   g_batch[NUM_N];
__device__ int   g_deg[NUM_N];       // zeroed for next replay in pool phase
__device__ float g_dinv[NUM_N];
__device__ int   g_woff[NUM_N];
__device__ int   g_csrc[NUM_E];
__device__ int   g_bsum[GRID];
__device__ int   g_pcnt[NUM_G];      // zeroed for next replay in prop1 phase
__device__ int   g_pcnt2[NUM_G];     // pristine copy for pool/mlp
__device__ int   g_boff[NUM_G];      // working copy (consumed by scatter)
__device__ int   g_boff2[NUM_G];     // pristine copy (pool start offsets)
__device__ int   g_bnode[NUM_N];
__device__ float g_h1[NUM_N * 16];
__device__ float g_q [NUM_N * 16];
__device__ float g_r [NUM_N * 16];

// -------- software grid barrier (7 slots, cyclic self-reset) --------------
__device__ __forceinline__ void grid_sync(int j) {
    __syncthreads();
    __threadfence();                       // release + L1 flush (CCTL.IVALL)
    if (threadIdx.x == 0) {
        if (atomicAdd(&g_bar[j], 1) == GRID - 1) {
            atomicExch(&g_bar[(j + 5) % 7], 0);   // reset a stale slot
        } else {
            while (atomicAdd(&g_bar[j], 0) < GRID) { }
        }
    }
    __syncthreads();
    __threadfence();                       // acquire + L1 flush
}

__global__ __launch_bounds__(TPB, 1) void mega_kernel(
    const float* __restrict__ x, const void* ei, const void* bat,
    const float* __restrict__ W1, const float* __restrict__ b1,
    const float* __restrict__ W2, const float* __restrict__ b2,
    const float* __restrict__ LW1, const float* __restrict__ Lb1,
    const float* __restrict__ LW2, const float* __restrict__ Lb2,
    float* __restrict__ out)
{
    __shared__ float4 w1s[512];      // W1 (8KB), later reused logically by w2s
    __shared__ float4 w2s[512];
    __shared__ float4 red[1024];     // pool partials (16KB)
    __shared__ int    wsum[32];
    __shared__ int    s_i32;
    __shared__ float  ps[128], z1[128], z2[2];

    const int tid  = threadIdx.x, bid = blockIdx.x;
    const int lane = tid & 31,    wid = tid >> 5;
    const int gth  = bid * TPB + tid;
    const int gw   = gth >> 5;

    // ---- detect int64 vs int32 index layout (per block, 64 samples) ----
    if (tid == 0) s_i32 = 0;
    __syncthreads();
    if (tid < 64) {
        long long v = ((const long long*)ei)[(size_t)tid * (NUM_E / 64)];
        if (v < 0 || v >= (long long)NUM_N) s_i32 = 1;
    }
    __syncthreads();
    const bool f64 = (s_i32 == 0);

    // ================= P0: degree+batch histograms, then gemm1 =============
    for (int i = gth; i < NUM_E; i += GT) {
        int d = f64 ? (int)((const long long*)ei)[NUM_E + i]
                    : ((const int*)ei)[NUM_E + i];
        atomicAdd(&g_deg[d], 1);
    }
    for (int i = gth; i < NUM_N; i += GT) {
        int b = f64 ? (int)((const long long*)bat)[i] : ((const int*)bat)[i];
        g_batch[i] = b;
        atomicAdd(&g_pcnt[b], 1);
    }
    for (int i = tid; i < 512; i += TPB) w1s[i] = ((const float4*)W1)[i];
    __syncthreads();
    for (int w = gw; w < NUM_N; w += NWARP) {
        float4 xv = ((const float4*)x)[(size_t)w * 32 + lane];
        float a[16];
        #pragma unroll
        for (int j = 0; j < 16; j++) a[j] = 0.f;
        {
            float xs[4] = {xv.x, xv.y, xv.z, xv.w};
            int kb4 = lane * 16;
            #pragma unroll
            for (int kk = 0; kk < 4; kk++) {
                float c = xs[kk];
                #pragma unroll
                for (int q = 0; q < 4; q++) {
                    float4 wv = w1s[kb4 + kk * 4 + q];
                    a[q*4+0] = fmaf(c, wv.x, a[q*4+0]);
                    a[q*4+1] = fmaf(c, wv.y, a[q*4+1]);
                    a[q*4+2] = fmaf(c, wv.z, a[q*4+2]);
                    a[q*4+3] = fmaf(c, wv.w, a[q*4+3]);
                }
            }
        }
        // halving butterfly: 16 outputs over 32 lanes
        {
            float t[16];
            #pragma unroll
            for (int i = 0; i < 16; i++) t[i] = __shfl_xor_sync(~0u, a[i], 16);
            if ((lane & 16) == 0) { 
                #pragma unroll
                for (int i = 0; i < 8; i++) a[i] += t[i]; }
            else { 
                #pragma unroll
                for (int i = 0; i < 8; i++) a[i] = a[i+8] + t[i+8]; }
        }
        {
            float t[8];
            #pragma unroll
            for (int i = 0; i < 8; i++) t[i] = __shfl_xor_sync(~0u, a[i], 8);
            if ((lane & 8) == 0) { 
                #pragma unroll
                for (int i = 0; i < 4; i++) a[i] += t[i]; }
            else { 
                #pragma unroll
                for (int i = 0; i < 4; i++) a[i] = a[i+4] + t[i+4]; }
        }
        {
            float t[4];
            #pragma unroll
            for (int i = 0; i < 4; i++) t[i] = __shfl_xor_sync(~0u, a[i], 4);
            if ((lane & 4) == 0) { a[0] += t[0]; a[1] += t[1]; }
            else                 { a[0] = a[2] + t[2]; a[1] = a[3] + t[3]; }
        }
        {
            float t0 = __shfl_xor_sync(~0u, a[0], 2);
            float t1 = __shfl_xor_sync(~0u, a[1], 2);
            if ((lane & 2) == 0) a[0] += t0; else a[0] = a[1] + t1;
        }
        a[0] += __shfl_xor_sync(~0u, a[0], 1);
        if ((lane & 1) == 0) g_h1[(size_t)w * 16 + (lane >> 1)] = a[0];
    }
    grid_sync(0);

    // ================= P1a: block-local scan of deg (+dinv, batch scan) ====
    const int node = bid * CHUNK + tid;
    const bool nvalid = (tid < CHUNK) && (node < NUM_N);
    int deg = nvalid ? g_deg[node] : 0;
    int v = deg;
    #pragma unroll
    for (int o = 1; o < 32; o <<= 1) {
        int n = __shfl_up_sync(~0u, v, o);
        if (lane >= o) v += n;
    }
    if (lane == 31) wsum[wid] = v;
    __syncthreads();
    if (wid == 0) {
        int wv = wsum[lane];
        #pragma unroll
        for (int o = 1; o < 32; o <<= 1) {
            int n = __shfl_up_sync(~0u, wv, o);
            if (lane >= o) wv += n;
        }
        wsum[lane] = wv;
    }
    __syncthreads();
    const int ex_local = (wid ? wsum[wid - 1] : 0) + v - deg;
    if (tid == 0) g_bsum[bid] = wsum[31];
    if (nvalid) g_dinv[node] = rsqrtf((float)deg + 1.f);
    if (bid == 0 && wid == 31) {   // batch scan + pristine copies
        int p0 = g_pcnt[lane*4+0], p1 = g_pcnt[lane*4+1];
        int p2 = g_pcnt[lane*4+2], p3 = g_pcnt[lane*4+3];
        int t1 = p0 + p1, t2 = t1 + p2, t3 = t2 + p3;
        int vv = t3;
        #pragma unroll
        for (int o = 1; o < 32; o <<= 1) {
            int n = __shfl_up_sync(~0u, vv, o);
            if (lane >= o) vv += n;
        }
        int exb = vv - t3;
        g_boff [lane*4+0] = exb;      g_boff2[lane*4+0] = exb;
        g_boff [lane*4+1] = exb+p0;   g_boff2[lane*4+1] = exb+p0;
        g_boff [lane*4+2] = exb+t1;   g_boff2[lane*4+2] = exb+t1;
        g_boff [lane*4+3] = exb+t2;   g_boff2[lane*4+3] = exb+t2;
        g_pcnt2[lane*4+0] = p0; g_pcnt2[lane*4+1] = p1;
        g_pcnt2[lane*4+2] = p2; g_pcnt2[lane*4+3] = p3;
    }
    grid_sync(1);

    // ================= P1b: scan the 148 block sums (block 0, warp 0) ======
    if (bid == 0 && tid < 32) {
        int carry = 0;
        #pragma unroll
        for (int c = 0; c < 5; c++) {
            int idx = c * 32 + tid;
            int vv = (idx < GRID) ? g_bsum[idx] : 0;
            int s = vv;
            #pragma unroll
            for (int o = 1; o < 32; o <<= 1) {
                int n = __shfl_up_sync(~0u, s, o);
                if (tid >= o) s += n;
            }
            if (idx < GRID) g_bsum[idx] = carry + s - vv;
            carry += __shfl_sync(~0u, s, 31);
        }
    }
    grid_sync(2);

    // ================= P1c: finalize CSR offsets ===========================
    if (nvalid) g_woff[node] = ex_local + g_bsum[bid];
    grid_sync(3);

    // ================= P2: scatter edges, bnode, prescale h1 ===============
    for (int i = gth; i < NUM_E; i += GT) {
        int s, d;
        if (f64) {
            s = (int)((const long long*)ei)[i];
            d = (int)((const long long*)ei)[NUM_E + i];
        } else {
            s = ((const int*)ei)[i];
            d = ((const int*)ei)[NUM_E + i];
        }
        g_csrc[atomicAdd(&g_woff[d], 1)] = s;
    }
    for (int i = gth; i < NUM_N; i += GT) {
        int b = g_batch[i];
        g_bnode[atomicAdd(&g_boff[b], 1)] = i;
    }
    for (int i = gth; i < NUM_N * 4; i += GT) {
        float dv = g_dinv[i >> 2];
        float4 vv = ((float4*)g_h1)[i];
        vv.x *= dv; vv.y *= dv; vv.z *= dv; vv.w *= dv;
        ((float4*)g_h1)[i] = vv;
    }
    grid_sync(4);

    // ================= P3: prop1 (+zero pcnt for next replay) ==============
    if (bid == GRID - 1 && tid < NUM_G) g_pcnt[tid] = 0;
    for (int w = gw; w < NUM_N; w += NWARP) {
        int sub = lane & 3, grp = lane >> 2;
        int dg = g_deg[w];
        int start = g_woff[w] - dg;
        float ax = 0.f, ay = 0.f, az = 0.f, aw = 0.f;
        for (int e = grp; e < dg; e += 8) {
            int s = g_csrc[start + e];
            float4 vv = ((const float4*)g_h1)[s * 4 + sub];
            ax += vv.x; ay += vv.y; az += vv.z; aw += vv.w;
        }
        #pragma unroll
        for (int o = 4; o < 32; o <<= 1) {
            ax += __shfl_xor_sync(~0u, ax, o);
            ay += __shfl_xor_sync(~0u, ay, o);
            az += __shfl_xor_sync(~0u, az, o);
            aw += __shfl_xor_sync(~0u, aw, o);
        }
        if (lane < 4) {
            float dvd = g_dinv[w];
            float4 hs = ((const float4*)g_h1)[w * 4 + sub];
            float4 bv = ((const float4*)b1)[sub];
            float4 o;
            o.x = fmaxf(fmaf(dvd, ax + hs.x, bv.x), 0.f) * dvd;
            o.y = fmaxf(fmaf(dvd, ay + hs.y, bv.y), 0.f) * dvd;
            o.z = fmaxf(fmaf(dvd, az + hs.z, bv.z), 0.f) * dvd;
            o.w = fmaxf(fmaf(dvd, aw + hs.w, bv.w), 0.f) * dvd;
            ((float4*)g_q)[w * 4 + sub] = o;
        }
    }
    grid_sync(5);

    // ================= P4: prop2 ===========================================
    for (int w = gw; w < NUM_N; w += NWARP) {
        int sub = lane & 3, grp = lane >> 2;
        int dg = g_deg[w];
        int start = g_woff[w] - dg;
        float ax = 0.f, ay = 0.f, az = 0.f, aw = 0.f;
        for (int e = grp; e < dg; e += 8) {
            int s = g_csrc[start + e];
            float4 vv = ((const float4*)g_q)[s * 4 + sub];
            ax += vv.x; ay += vv.y; az += vv.z; aw += vv.w;
        }
        #pragma unroll
        for (int o = 4; o < 32; o <<= 1) {
            ax += __shfl_xor_sync(~0u, ax, o);
            ay += __shfl_xor_sync(~0u, ay, o);
            az += __shfl_xor_sync(~0u, az, o);
            aw += __shfl_xor_sync(~0u, aw, o);
        }
        if (lane < 4) {
            float dvd = g_dinv[w];
            float4 qs = ((const float4*)g_q)[w * 4 + sub];
            float4 o;
            o.x = dvd * (ax + qs.x); o.y = dvd * (ay + qs.y);
            o.z = dvd * (az + qs.z); o.w = dvd * (aw + qs.w);
            ((float4*)g_r)[w * 4 + sub] = o;
        }
    }
    grid_sync(6);

    // ================= P5: pool + gemm2 + mlp (blocks 0..127) ==============
    if (bid < NUM_G) {
        for (int i = tid; i < 512; i += TPB) w2s[i] = ((const float4*)W2)[i];
        __syncthreads();
        const int g = bid;
        const int cnt = g_pcnt2[g];
        const int start = g_boff2[g];
        float4 bv = ((const float4*)b2)[lane];
        float4 sum = make_float4(0.f, 0.f, 0.f, 0.f);
        for (int i = wid; i < cnt; i += 32) {
            int n = g_bnode[start + i];
            float rv = (lane < 16) ? g_r[n * 16 + lane] : 0.f;
            float4 acc = bv;
            #pragma unroll
            for (int k = 0; k < 16; k++) {
                float s = __shfl_sync(~0u, rv, k);
                float4 wv = w2s[k * 32 + lane];
                acc.x = fmaf(s, wv.x, acc.x); acc.y = fmaf(s, wv.y, acc.y);
                acc.z = fmaf(s, wv.z, acc.z); acc.w = fmaf(s, wv.w, acc.w);
            }
            sum.x += fmaxf(acc.x, 0.f); sum.y += fmaxf(acc.y, 0.f);
            sum.z += fmaxf(acc.z, 0.f); sum.w += fmaxf(acc.w, 0.f);
        }
        red[wid * 32 + lane] = sum;
        __syncthreads();
        if (tid < 32) {
            float4 tot = red[tid];
            #pragma unroll
            for (int w2 = 1; w2 < 32; w2++) {
                float4 vv = red[w2 * 32 + tid];
                tot.x += vv.x; tot.y += vv.y; tot.z += vv.z; tot.w += vv.w;
            }
            float inv = 1.f / fmaxf((float)cnt, 1.f);
            ps[tid * 4 + 0] = tot.x * inv; ps[tid * 4 + 1] = tot.y * inv;
            ps[tid * 4 + 2] = tot.z * inv; ps[tid * 4 + 3] = tot.w * inv;
        }
        __syncthreads();
        if (tid < 128) {
            float acc = Lb1[tid];
            #pragma unroll 8
            for (int k = 0; k < 128; k++) acc = fmaf(ps[k], LW1[k * 128 + tid], acc);
            z1[tid] = fmaxf(acc, 0.f);
        }
        __syncthreads();
        if (tid < 2) {
            float a = Lb2[tid];
            for (int k = 0; k < 128; k++) a = fmaf(z1[k], LW2[k * 2 + tid], a);
            z2[tid] = a;
        }
        __syncthreads();
        if (tid == 0) {
            float m = fmaxf(z2[0], z2[1]);
            float lse = m + logf(expf(z2[0] - m) + expf(z2[1] - m));
            out[g * 2 + 0] = z2[0] - lse;
            out[g * 2 + 1] = z2[1] - lse;
        }
    } else {
        // idle blocks: zero g_deg for the next replay
        for (int i = (bid - NUM_G) * TPB + tid; i < NUM_N; i += (GRID - NUM_G) * TPB)
            g_deg[i] = 0;
    }
}

// -------- launch --------
extern "C" void kernel_launch(void* const* d_in, const int* in_sizes, int n_in,
                              void* d_out, int out_size) {
    const float* x   = (const float*)d_in[0];
    const void*  ei  = d_in[1];
    const void*  bat = d_in[2];
    const float* W1  = (const float*)d_in[3];
    const float* b1  = (const float*)d_in[4];
    const float* W2  = (const float*)d_in[5];
    const float* b2  = (const float*)d_in[6];
    const float* LW1 = (const float*)d_in[7];
    const float* Lb1 = (const float*)d_in[8];
    const float* LW2 = (const float*)d_in[9];
    const float* Lb2 = (const float*)d_in[10];
    float* out = (float*)d_out;

    mega_kernel<<<GRID, TPB>>>(x, ei, bat, W1, b1, W2, b2,
                               LW1, Lb1, LW2, Lb2, out);
}